// round 4
// baseline (speedup 1.0000x reference)
#include <cuda_runtime.h>

// Problem constants (static shapes from reference)
#define N_TOK 8192
#define H_DIM 1024
#define F_DIM 4096
#define E_NUM 8
#define K_CAP 1280   // int(8192 * 1.25 / 8)

// ---------------- scratch (static __device__ globals, no allocation) --------
__device__ unsigned long long g_keys[E_NUM * N_TOK];         // 512 KB
__device__ unsigned long long g_part[E_NUM * 2 * K_CAP];     // 160 KB
__device__ int   g_indices[E_NUM * K_CAP];                   // 40 KB
__device__ int   g_slot[N_TOK * E_NUM];                      // 256 KB
__device__ float g_h [(size_t)E_NUM * K_CAP * F_DIM];        // 167.8 MB
__device__ float g_eo[(size_t)E_NUM * K_CAP * H_DIM];        //  41.9 MB

// ---------------- gating: fp64-accurate logits -> sortable 64-bit keys ------
__global__ void gate_kernel(const float* __restrict__ x,
                            const float* __restrict__ gw) {
    int t = blockIdx.x;
    int tid = threadIdx.x;
    double acc[E_NUM];
#pragma unroll
    for (int e = 0; e < E_NUM; ++e) acc[e] = 0.0;

    const float* xr = x + (size_t)t * H_DIM;
    for (int h = tid; h < H_DIM; h += 256) {
        double xv = (double)xr[h];
        const float* g = gw + h * E_NUM;
#pragma unroll
        for (int e = 0; e < E_NUM; ++e) acc[e] += xv * (double)g[e];
    }
    // warp reduce
#pragma unroll
    for (int e = 0; e < E_NUM; ++e) {
#pragma unroll
        for (int off = 16; off > 0; off >>= 1)
            acc[e] += __shfl_down_sync(0xffffffffu, acc[e], off);
    }
    __shared__ double red[8][E_NUM];
    int warp = tid >> 5, lane = tid & 31;
    if (lane == 0) {
#pragma unroll
        for (int e = 0; e < E_NUM; ++e) red[warp][e] = acc[e];
    }
    __syncthreads();
    if (tid < E_NUM) {
        double s = 0.0;
        for (int w = 0; w < 8; ++w) s += red[w][tid];
        float lf = (float)s;
        unsigned u = __float_as_uint(lf);
        u = (u & 0x80000000u) ? ~u : (u | 0x80000000u);   // monotonic map
        unsigned long long key =
            ((unsigned long long)u << 13) | (unsigned)(8191 - t); // tiebreak: lower t wins
        g_keys[tid * N_TOK + t] = key;
        g_slot[t * E_NUM + tid] = -1;   // re-init inverse map every call
    }
}

// ---------------- per-expert half-sort (bitonic, 4096 elems, 32KB smem) -----
__global__ void sort_half_kernel() {
    __shared__ unsigned long long s[4096];
    int e = blockIdx.y, half = blockIdx.x;
    const unsigned long long* keys = g_keys + e * N_TOK + half * 4096;
    for (int i = threadIdx.x; i < 4096; i += 1024) s[i] = ~keys[i]; // asc of ~k = desc of k
    __syncthreads();
    for (int k = 2; k <= 4096; k <<= 1) {
        for (int j = k >> 1; j > 0; j >>= 1) {
            for (int base = 0; base < 4096; base += 1024) {
                int i = base + threadIdx.x;
                int l = i ^ j;
                if (l > i) {
                    unsigned long long a = s[i], b = s[l];
                    bool up = ((i & k) == 0);
                    if (up ? (a > b) : (a < b)) { s[i] = b; s[l] = a; }
                }
            }
            __syncthreads();
        }
    }
    // first K_CAP entries = largest keys of this half (restore original keys)
    for (int i = threadIdx.x; i < K_CAP; i += 1024)
        g_part[(e * 2 + half) * K_CAP + i] = ~s[i];
}

// ---------------- merge the two sorted half-lists by rank -------------------
__global__ void merge_topk_kernel() {
    int e = blockIdx.x;
    const unsigned long long* A = g_part + (size_t)(e * 2 + 0) * K_CAP;
    const unsigned long long* B = g_part + (size_t)(e * 2 + 1) * K_CAP;
    for (int idx = threadIdx.x; idx < 2 * K_CAP; idx += blockDim.x) {
        bool inA = idx < K_CAP;
        const unsigned long long* other = inA ? B : A;
        int i = inA ? idx : idx - K_CAP;
        unsigned long long v = (inA ? A : B)[i];
        // count entries of `other` strictly greater than v (keys are all distinct)
        int lo = 0, hi = K_CAP;
        while (lo < hi) {
            int mid = (lo + hi) >> 1;
            if (other[mid] > v) lo = mid + 1; else hi = mid;
        }
        int rank = i + lo;
        if (rank < K_CAP) {
            int t = 8191 - (int)(v & 0x1FFFull);
            g_indices[e * K_CAP + rank] = t;
            g_slot[t * E_NUM + e] = rank;
        }
    }
}

// ---------------- GEMM helpers ----------------------------------------------
__device__ __forceinline__ float silu_f(float v) {
    return v / (1.0f + expf(-v));
}

// GEMM1: h[e] = silu( gather(x, idx[e]) @ w1[e] )   M=1280 N=4096 K=1024
__global__ __launch_bounds__(256)
void gemm1_kernel(const float* __restrict__ x, const float* __restrict__ w1) {
    __shared__ __align__(16) float As[8][132];
    __shared__ __align__(16) float Bs[8][128];
    __shared__ int stok[128];

    int e = blockIdx.z, by = blockIdx.y, bx = blockIdx.x;
    int tid = threadIdx.x;
    int tx = tid & 15, ty = tid >> 4;

    if (tid < 128) stok[tid] = g_indices[e * K_CAP + by * 128 + tid];
    __syncthreads();

    int ar = tid >> 1, ak4 = (tid & 1) << 2;
    const float* aptr = x + (size_t)stok[ar] * H_DIM + ak4;
    int bk = tid >> 5, bc4 = (tid & 31) << 2;
    const float* bptr = w1 + (size_t)e * H_DIM * F_DIM
                        + (size_t)bk * F_DIM + bx * 128 + bc4;

    float acc[8][8];
#pragma unroll
    for (int i = 0; i < 8; ++i)
#pragma unroll
        for (int j = 0; j < 8; ++j) acc[i][j] = 0.0f;

    for (int kt = 0; kt < H_DIM / 8; ++kt) {
        float4 av = *(const float4*)(aptr + kt * 8);
        float4 bv = *(const float4*)(bptr + (size_t)(kt * 8) * F_DIM);
        __syncthreads();
        As[ak4 + 0][ar] = av.x; As[ak4 + 1][ar] = av.y;
        As[ak4 + 2][ar] = av.z; As[ak4 + 3][ar] = av.w;
        *(float4*)&Bs[bk][bc4] = bv;
        __syncthreads();
#pragma unroll
        for (int kk = 0; kk < 8; ++kk) {
            float4 a0 = *(const float4*)&As[kk][ty * 8];
            float4 a1 = *(const float4*)&As[kk][ty * 8 + 4];
            float4 b0 = *(const float4*)&Bs[kk][tx * 8];
            float4 b1 = *(const float4*)&Bs[kk][tx * 8 + 4];
            float a[8] = {a0.x, a0.y, a0.z, a0.w, a1.x, a1.y, a1.z, a1.w};
            float b[8] = {b0.x, b0.y, b0.z, b0.w, b1.x, b1.y, b1.z, b1.w};
#pragma unroll
            for (int i = 0; i < 8; ++i)
#pragma unroll
                for (int j = 0; j < 8; ++j)
                    acc[i][j] = fmaf(a[i], b[j], acc[i][j]);
        }
    }

    size_t base = ((size_t)e * K_CAP + (size_t)by * 128 + ty * 8) * F_DIM
                  + (size_t)bx * 128 + tx * 8;
#pragma unroll
    for (int i = 0; i < 8; ++i) {
        float4 v0, v1;
        v0.x = silu_f(acc[i][0]); v0.y = silu_f(acc[i][1]);
        v0.z = silu_f(acc[i][2]); v0.w = silu_f(acc[i][3]);
        v1.x = silu_f(acc[i][4]); v1.y = silu_f(acc[i][5]);
        v1.z = silu_f(acc[i][6]); v1.w = silu_f(acc[i][7]);
        *(float4*)(g_h + base + (size_t)i * F_DIM)     = v0;
        *(float4*)(g_h + base + (size_t)i * F_DIM + 4) = v1;
    }
}

// GEMM2: eo[e] = h[e] @ w2[e]    M=1280 N=1024 K=4096
__global__ __launch_bounds__(256)
void gemm2_kernel(const float* __restrict__ w2) {
    __shared__ __align__(16) float As[8][132];
    __shared__ __align__(16) float Bs[8][128];

    int e = blockIdx.z, by = blockIdx.y, bx = blockIdx.x;
    int tid = threadIdx.x;
    int tx = tid & 15, ty = tid >> 4;

    int ar = tid >> 1, ak4 = (tid & 1) << 2;
    const float* aptr = g_h + ((size_t)e * K_CAP + (size_t)by * 128 + ar) * F_DIM + ak4;
    int bk = tid >> 5, bc4 = (tid & 31) << 2;
    const float* bptr = w2 + (size_t)e * F_DIM * H_DIM
                        + (size_t)bk * H_DIM + bx * 128 + bc4;

    float acc[8][8];
#pragma unroll
    for (int i = 0; i < 8; ++i)
#pragma unroll
        for (int j = 0; j < 8; ++j) acc[i][j] = 0.0f;

    for (int kt = 0; kt < F_DIM / 8; ++kt) {
        float4 av = *(const float4*)(aptr + kt * 8);
        float4 bv = *(const float4*)(bptr + (size_t)(kt * 8) * H_DIM);
        __syncthreads();
        As[ak4 + 0][ar] = av.x; As[ak4 + 1][ar] = av.y;
        As[ak4 + 2][ar] = av.z; As[ak4 + 3][ar] = av.w;
        *(float4*)&Bs[bk][bc4] = bv;
        __syncthreads();
#pragma unroll
        for (int kk = 0; kk < 8; ++kk) {
            float4 a0 = *(const float4*)&As[kk][ty * 8];
            float4 a1 = *(const float4*)&As[kk][ty * 8 + 4];
            float4 b0 = *(const float4*)&Bs[kk][tx * 8];
            float4 b1 = *(const float4*)&Bs[kk][tx * 8 + 4];
            float a[8] = {a0.x, a0.y, a0.z, a0.w, a1.x, a1.y, a1.z, a1.w};
            float b[8] = {b0.x, b0.y, b0.z, b0.w, b1.x, b1.y, b1.z, b1.w};
#pragma unroll
            for (int i = 0; i < 8; ++i)
#pragma unroll
                for (int j = 0; j < 8; ++j)
                    acc[i][j] = fmaf(a[i], b[j], acc[i][j]);
        }
    }

    size_t base = ((size_t)e * K_CAP + (size_t)by * 128 + ty * 8) * H_DIM
                  + (size_t)bx * 128 + tx * 8;
#pragma unroll
    for (int i = 0; i < 8; ++i) {
        float4 v0, v1;
        v0.x = acc[i][0]; v0.y = acc[i][1]; v0.z = acc[i][2]; v0.w = acc[i][3];
        v1.x = acc[i][4]; v1.y = acc[i][5]; v1.z = acc[i][6]; v1.w = acc[i][7];
        *(float4*)(g_eo + base + (size_t)i * H_DIM)     = v0;
        *(float4*)(g_eo + base + (size_t)i * H_DIM + 4) = v1;
    }
}

// ---------------- deterministic scatter (fixed e-ascending sum order) -------
__global__ void scatter_kernel(float* __restrict__ out) {
    int t = blockIdx.x, tid = threadIdx.x;
    __shared__ int ssl[E_NUM];
    if (tid < E_NUM) ssl[tid] = g_slot[t * E_NUM + tid];
    __syncthreads();
    int j = tid * 4;  // 256 threads * 4 = 1024 = H_DIM
    float4 sum = make_float4(0.f, 0.f, 0.f, 0.f);
#pragma unroll
    for (int e = 0; e < E_NUM; ++e) {
        int sl = ssl[e];
        if (sl >= 0) {
            float4 v = *(const float4*)(g_eo + ((size_t)e * K_CAP + sl) * H_DIM + j);
            sum.x += v.x; sum.y += v.y; sum.z += v.z; sum.w += v.w;
        }
    }
    *(float4*)(out + (size_t)t * H_DIM + j) = sum;
}

// ---------------- launch ----------------------------------------------------
extern "C" void kernel_launch(void* const* d_in, const int* in_sizes, int n_in,
                              void* d_out, int out_size) {
    const float* x  = (const float*)d_in[0];   // [4,2048,1024]
    const float* gw = (const float*)d_in[1];   // [1024,8]
    const float* w1 = (const float*)d_in[2];   // [8,1024,4096]
    const float* w2 = (const float*)d_in[3];   // [8,4096,1024]
    float* out = (float*)d_out;                // [4,2048,1024] (+ loss scalar = 0)

    (void)in_sizes; (void)n_in;

    // zero everything incl. the load-balancing loss (exactly 0: load == k for all experts)
    cudaMemsetAsync(d_out, 0, (size_t)out_size * sizeof(float), 0);

    gate_kernel<<<N_TOK, 256>>>(x, gw);
    sort_half_kernel<<<dim3(2, E_NUM), 1024>>>();
    merge_topk_kernel<<<E_NUM, 256>>>();
    gemm1_kernel<<<dim3(F_DIM / 128, K_CAP / 128, E_NUM), 256>>>(x, w1);
    gemm2_kernel<<<dim3(H_DIM / 128, K_CAP / 128, E_NUM), 256>>>(w2);
    scatter_kernel<<<N_TOK, 256>>>(out);
}

// round 8
// speedup vs baseline: 1.7323x; 1.7323x over previous
#include <cuda_runtime.h>
#include <cuda_bf16.h>

// ---------------- problem constants -----------------------------------------
#define N_TOK 8192
#define H_DIM 1024
#define F_DIM 4096
#define E_NUM 8
#define K_CAP 1280   // int(8192 * 1.25 / 8)

// ---------------- scratch (static device globals, exactly R3 topology) ------
__device__ unsigned long long g_keys[E_NUM * N_TOK];
__device__ unsigned long long g_part[E_NUM * 2 * K_CAP];
__device__ int   g_indices[E_NUM * K_CAP];
__device__ int   g_slot[N_TOK * E_NUM];
__device__ float g_h [(size_t)E_NUM * K_CAP * F_DIM];   // fp32, as in passing R3
__device__ float g_eo[(size_t)E_NUM * K_CAP * H_DIM];   // fp32, as in passing R3

// ---------------- helpers -----------------------------------------------------
__device__ __forceinline__ unsigned smem_u32(const void* p) {
    unsigned a;
    asm("{ .reg .u64 t; cvta.to.shared.u64 t, %1; cvt.u32.u64 %0, t; }" : "=r"(a) : "l"(p));
    return a;
}
__device__ __forceinline__ void ldsm4(unsigned& r0, unsigned& r1, unsigned& r2,
                                      unsigned& r3, unsigned addr) {
    asm volatile("ldmatrix.sync.aligned.m8n8.x4.shared.b16 {%0,%1,%2,%3}, [%4];"
                 : "=r"(r0), "=r"(r1), "=r"(r2), "=r"(r3) : "r"(addr));
}
__device__ __forceinline__ void ldsm4t(unsigned& r0, unsigned& r1, unsigned& r2,
                                       unsigned& r3, unsigned addr) {
    asm volatile("ldmatrix.sync.aligned.m8n8.x4.trans.shared.b16 {%0,%1,%2,%3}, [%4];"
                 : "=r"(r0), "=r"(r1), "=r"(r2), "=r"(r3) : "r"(addr));
}
__device__ __forceinline__ void mma16816(float* c, const unsigned* a, const unsigned* b) {
    asm volatile("mma.sync.aligned.m16n8k16.row.col.f32.bf16.bf16.f32 "
                 "{%0,%1,%2,%3}, {%4,%5,%6,%7}, {%8,%9}, {%0,%1,%2,%3};"
                 : "+f"(c[0]), "+f"(c[1]), "+f"(c[2]), "+f"(c[3])
                 : "r"(a[0]), "r"(a[1]), "r"(a[2]), "r"(a[3]), "r"(b[0]), "r"(b[1]));
}
__device__ __forceinline__ unsigned pack_bf2(float x, float y) {
    __nv_bfloat162 p = __halves2bfloat162(__float2bfloat16(x), __float2bfloat16(y));
    return *reinterpret_cast<unsigned*>(&p);
}
// split float4 into packed hi (2x u32) and lo (2x u32)
__device__ __forceinline__ void cvt_split4(float4 v, uint2& hi, uint2& lo) {
    float hx = __bfloat162float(__float2bfloat16(v.x));
    float hy = __bfloat162float(__float2bfloat16(v.y));
    float hz = __bfloat162float(__float2bfloat16(v.z));
    float hw = __bfloat162float(__float2bfloat16(v.w));
    hi.x = pack_bf2(v.x, v.y);
    hi.y = pack_bf2(v.z, v.w);
    lo.x = pack_bf2(v.x - hx, v.y - hy);
    lo.y = pack_bf2(v.z - hz, v.w - hw);
}
__device__ __forceinline__ float silu_f(float v) { return v / (1.0f + expf(-v)); }

// ---------------- gating: fp64-accurate logits -> sortable 64-bit keys ------
__global__ void gate_kernel(const float* __restrict__ x,
                            const float* __restrict__ gw) {
    int t = blockIdx.x;
    int tid = threadIdx.x;
    double acc[E_NUM];
#pragma unroll
    for (int e = 0; e < E_NUM; ++e) acc[e] = 0.0;
    const float* xr = x + (size_t)t * H_DIM;
    for (int h = tid; h < H_DIM; h += 256) {
        double xv = (double)xr[h];
        const float* g = gw + h * E_NUM;
#pragma unroll
        for (int e = 0; e < E_NUM; ++e) acc[e] += xv * (double)g[e];
    }
#pragma unroll
    for (int e = 0; e < E_NUM; ++e) {
#pragma unroll
        for (int off = 16; off > 0; off >>= 1)
            acc[e] += __shfl_down_sync(0xffffffffu, acc[e], off);
    }
    __shared__ double red[8][E_NUM];
    int warp = tid >> 5, lane = tid & 31;
    if (lane == 0) {
#pragma unroll
        for (int e = 0; e < E_NUM; ++e) red[warp][e] = acc[e];
    }
    __syncthreads();
    if (tid < E_NUM) {
        double s = 0.0;
        for (int w = 0; w < 8; ++w) s += red[w][tid];
        float lf = (float)s;
        unsigned u = __float_as_uint(lf);
        u = (u & 0x80000000u) ? ~u : (u | 0x80000000u);
        unsigned long long key =
            ((unsigned long long)u << 13) | (unsigned)(8191 - t);
        g_keys[tid * N_TOK + t] = key;
        g_slot[t * E_NUM + tid] = -1;
    }
}

// ---------------- per-expert half-sort (bitonic, 4096 elems) ----------------
__global__ void sort_half_kernel() {
    __shared__ unsigned long long s[4096];
    int e = blockIdx.y, half = blockIdx.x;
    const unsigned long long* keys = g_keys + e * N_TOK + half * 4096;
    for (int i = threadIdx.x; i < 4096; i += 1024) s[i] = ~keys[i];
    __syncthreads();
    for (int k = 2; k <= 4096; k <<= 1) {
        for (int j = k >> 1; j > 0; j >>= 1) {
            for (int base = 0; base < 4096; base += 1024) {
                int i = base + threadIdx.x;
                int l = i ^ j;
                if (l > i) {
                    unsigned long long a = s[i], b = s[l];
                    bool up = ((i & k) == 0);
                    if (up ? (a > b) : (a < b)) { s[i] = b; s[l] = a; }
                }
            }
            __syncthreads();
        }
    }
    for (int i = threadIdx.x; i < K_CAP; i += 1024)
        g_part[(e * 2 + half) * K_CAP + i] = ~s[i];
}

// ---------------- merge the two sorted half-lists by rank -------------------
__global__ void merge_topk_kernel() {
    int e = blockIdx.x;
    const unsigned long long* A = g_part + (size_t)(e * 2 + 0) * K_CAP;
    const unsigned long long* B = g_part + (size_t)(e * 2 + 1) * K_CAP;
    for (int idx = threadIdx.x; idx < 2 * K_CAP; idx += blockDim.x) {
        bool inA = idx < K_CAP;
        const unsigned long long* other = inA ? B : A;
        int i = inA ? idx : idx - K_CAP;
        unsigned long long v = (inA ? A : B)[i];
        int lo = 0, hi = K_CAP;
        while (lo < hi) {
            int mid = (lo + hi) >> 1;
            if (other[mid] > v) lo = mid + 1; else hi = mid;
        }
        int rank = i + lo;
        if (rank < K_CAP) {
            int t = 8191 - (int)(v & 0x1FFFull);
            g_indices[e * K_CAP + rank] = t;
            g_slot[t * E_NUM + e] = rank;
        }
    }
}

// ---------------- HMMA GEMM: 128x128 tile, BK=32, in-kernel bf16 split ------
// A tiles (hi/lo): [128 rows m][32 k] bf16, 64B rows, 16B-unit swizzle u^=(m&3)
// B tiles (hi/lo): [32 rows k][128 n] bf16, 256B rows, 16B-unit swizzle u^=(k&7)
// 256 threads = 8 warps (2m x 4n), warp tile 64x32.
template<bool FIRST>
__global__ __launch_bounds__(256)
void moe_gemm_kernel(const float* __restrict__ x,
                     const float* __restrict__ w) {
    constexpr int KNAT = FIRST ? H_DIM : F_DIM;
    constexpr int NEXP = FIRST ? F_DIM : H_DIM;
    constexpr int NCH  = KNAT / 32;

    __shared__ __align__(16) unsigned char smA[2][8192];  // [hi/lo][128*64B]
    __shared__ __align__(16) unsigned char smB[2][8192];  // [hi/lo][32*256B]

    const int tid  = threadIdx.x;
    const int wid  = tid >> 5, lane = tid & 31;
    const int e    = blockIdx.z;
    const int m0   = blockIdx.y * 128, n0 = blockIdx.x * 128;
    const int wm   = (wid >> 2) * 64;
    const int wn   = (wid & 3) * 32;

    const unsigned baseAh = smem_u32(smA[0]), baseAl = smem_u32(smA[1]);
    const unsigned baseBh = smem_u32(smB[0]), baseBl = smem_u32(smB[1]);

    // ---- staging source pointers (R3-style addressing, fp32 global) ----
    const int arow = tid >> 1, ahalf = tid & 1;      // 128 rows x 2 halves
    const float* aptr;
    if (FIRST) {
        int tok = g_indices[e * K_CAP + m0 + arow];
        aptr = x + (size_t)tok * H_DIM + ahalf * 16;
    } else {
        aptr = g_h + ((size_t)e * K_CAP + m0 + arow) * F_DIM + ahalf * 16;
    }
    const int brow = tid >> 3, bcol = tid & 7;       // 32 rows x 8 col-blocks
    const float* bptr = w + (size_t)e * KNAT * NEXP
                        + (size_t)brow * NEXP + n0 + bcol * 16;

    float acc[4][4][4];
#pragma unroll
    for (int mt = 0; mt < 4; ++mt)
#pragma unroll
        for (int nt = 0; nt < 4; ++nt)
#pragma unroll
            for (int q = 0; q < 4; ++q) acc[mt][nt][q] = 0.0f;

    for (int kt = 0; kt < NCH; ++kt) {
        __syncthreads();
        // ---- stage A (fp32 -> bf16 hi/lo) ----
        {
            const float* src = aptr + kt * 32;
#pragma unroll
            for (int j = 0; j < 4; ++j) {
                float4 v = *(const float4*)(src + j * 4);
                uint2 hi, lo;
                cvt_split4(v, hi, lo);
                unsigned unit = (unsigned)(ahalf * 2 + (j >> 1));
                unsigned addr = (unsigned)arow * 64u
                              + ((unit ^ ((unsigned)arow & 3u)) * 16u)
                              + (j & 1) * 8u;
                *(uint2*)(smA[0] + addr) = hi;
                *(uint2*)(smA[1] + addr) = lo;
            }
        }
        // ---- stage B ----
        {
            const float* src = bptr + (size_t)(kt * 32) * NEXP;
#pragma unroll
            for (int j = 0; j < 4; ++j) {
                float4 v = *(const float4*)(src + j * 4);
                uint2 hi, lo;
                cvt_split4(v, hi, lo);
                unsigned unit = (unsigned)(2 * bcol + (j >> 1));
                unsigned addr = (unsigned)brow * 256u
                              + ((unit ^ ((unsigned)brow & 7u)) * 16u)
                              + (j & 1) * 8u;
                *(uint2*)(smB[0] + addr) = hi;
                *(uint2*)(smB[1] + addr) = lo;
            }
        }
        __syncthreads();

        // ---- compute: 2 k16 steps, 3-term split ----
#pragma unroll
        for (int ks = 0; ks < 2; ++ks) {
            unsigned ah[4][4], al[4][4];
#pragma unroll
            for (int mt = 0; mt < 4; ++mt) {
                unsigned row = (unsigned)(wm + mt * 16 + (lane & 15));
                unsigned unit = (unsigned)(ks * 2 + (lane >> 4));
                unsigned off = row * 64u + ((unit ^ (row & 3u)) * 16u);
                ldsm4(ah[mt][0], ah[mt][1], ah[mt][2], ah[mt][3], baseAh + off);
                ldsm4(al[mt][0], al[mt][1], al[mt][2], al[mt][3], baseAl + off);
            }
            unsigned bh[4][2], bl[4][2];
#pragma unroll
            for (int p = 0; p < 2; ++p) {
                int g = lane >> 3;
                unsigned krow = (unsigned)(ks * 16 + (g & 1) * 8 + (lane & 7));
                unsigned unit = (unsigned)((wn >> 3) + 2 * p + (g >> 1));
                unsigned off = krow * 256u + ((unit ^ (krow & 7u)) * 16u);
                unsigned r0, r1, r2, r3;
                ldsm4t(r0, r1, r2, r3, baseBh + off);
                bh[2 * p][0] = r0;     bh[2 * p][1] = r1;
                bh[2 * p + 1][0] = r2; bh[2 * p + 1][1] = r3;
                ldsm4t(r0, r1, r2, r3, baseBl + off);
                bl[2 * p][0] = r0;     bl[2 * p][1] = r1;
                bl[2 * p + 1][0] = r2; bl[2 * p + 1][1] = r3;
            }
#pragma unroll
            for (int mt = 0; mt < 4; ++mt)
#pragma unroll
                for (int nt = 0; nt < 4; ++nt) {
                    mma16816(acc[mt][nt], ah[mt], bh[nt]);
                    mma16816(acc[mt][nt], al[mt], bh[nt]);
                    mma16816(acc[mt][nt], ah[mt], bl[nt]);
                }
        }
    }

    // ---- epilogue ----
#pragma unroll
    for (int mt = 0; mt < 4; ++mt) {
#pragma unroll
        for (int nt = 0; nt < 4; ++nt) {
            int row0 = m0 + wm + mt * 16 + (lane >> 2);
            int cc   = n0 + wn + nt * 8 + 2 * (lane & 3);
#pragma unroll
            for (int hrow = 0; hrow < 2; ++hrow) {
                float v0 = acc[mt][nt][2 * hrow + 0];
                float v1 = acc[mt][nt][2 * hrow + 1];
                if (FIRST) {
                    size_t g0 = ((size_t)e * K_CAP + row0 + 8 * hrow) * (size_t)F_DIM + cc;
                    float2 s;
                    s.x = silu_f(v0);
                    s.y = silu_f(v1);
                    *(float2*)(g_h + g0) = s;
                } else {
                    size_t g0 = ((size_t)e * K_CAP + row0 + 8 * hrow) * (size_t)H_DIM + cc;
                    float2 s;
                    s.x = v0;
                    s.y = v1;
                    *(float2*)(g_eo + g0) = s;
                }
            }
        }
    }
}

// ---------------- deterministic scatter (fixed e-ascending sum order) -------
__global__ void scatter_kernel(float* __restrict__ out) {
    int t = blockIdx.x, tid = threadIdx.x;
    __shared__ int ssl[E_NUM];
    if (tid < E_NUM) ssl[tid] = g_slot[t * E_NUM + tid];
    __syncthreads();
    int j = tid * 4;
    float4 sum = make_float4(0.f, 0.f, 0.f, 0.f);
#pragma unroll
    for (int e = 0; e < E_NUM; ++e) {
        int sl = ssl[e];
        if (sl >= 0) {
            float4 v = *(const float4*)(g_eo + ((size_t)e * K_CAP + sl) * H_DIM + j);
            sum.x += v.x; sum.y += v.y; sum.z += v.z; sum.w += v.w;
        }
    }
    *(float4*)(out + (size_t)t * H_DIM + j) = sum;
}

// ---------------- launch ----------------------------------------------------
extern "C" void kernel_launch(void* const* d_in, const int* in_sizes, int n_in,
                              void* d_out, int out_size) {
    const float* x  = (const float*)d_in[0];   // [4,2048,1024]
    const float* gw = (const float*)d_in[1];   // [1024,8]
    const float* w1 = (const float*)d_in[2];   // [8,1024,4096]
    const float* w2 = (const float*)d_in[3];   // [8,4096,1024]
    float* out = (float*)d_out;
    (void)in_sizes; (void)n_in;

    // loss scalar = 0 exactly (expert_load == k for all experts)
    cudaMemsetAsync(d_out, 0, (size_t)out_size * sizeof(float), 0);

    gate_kernel<<<N_TOK, 256>>>(x, gw);
    sort_half_kernel<<<dim3(2, E_NUM), 1024>>>();
    merge_topk_kernel<<<E_NUM, 256>>>();

    moe_gemm_kernel<true ><<<dim3(F_DIM / 128, K_CAP / 128, E_NUM), 256>>>(x, w1);
    moe_gemm_kernel<false><<<dim3(H_DIM / 128, K_CAP / 128, E_NUM), 256>>>(nullptr, w2);

    scatter_kernel<<<N_TOK, 256>>>(out);
}

// round 9
// speedup vs baseline: 2.5770x; 1.4876x over previous
#include <cuda_runtime.h>
#include <cuda_bf16.h>

// ---------------- problem constants -----------------------------------------
#define N_TOK 8192
#define H_DIM 1024
#define F_DIM 4096
#define E_NUM 8
#define K_CAP 1280   // int(8192 * 1.25 / 8)

// ---------------- scratch (static device globals, no allocation) ------------
__device__ unsigned long long g_keys[E_NUM * N_TOK];
__device__ unsigned long long g_part[E_NUM * 2 * K_CAP];
__device__ int   g_indices[E_NUM * K_CAP];
__device__ int   g_slot[N_TOK * E_NUM];
__device__ float g_h [(size_t)E_NUM * K_CAP * F_DIM];       // fp32 intermediate
__device__ float g_eo[(size_t)2 * E_NUM * K_CAP * H_DIM];   // 2 split-K planes

#define EOP ((size_t)E_NUM * K_CAP * H_DIM)

// ---------------- helpers -----------------------------------------------------
__device__ __forceinline__ unsigned smem_u32(const void* p) {
    unsigned a;
    asm("{ .reg .u64 t; cvta.to.shared.u64 t, %1; cvt.u32.u64 %0, t; }" : "=r"(a) : "l"(p));
    return a;
}
__device__ __forceinline__ void ldsm4(unsigned& r0, unsigned& r1, unsigned& r2,
                                      unsigned& r3, unsigned addr) {
    asm volatile("ldmatrix.sync.aligned.m8n8.x4.shared.b16 {%0,%1,%2,%3}, [%4];"
                 : "=r"(r0), "=r"(r1), "=r"(r2), "=r"(r3) : "r"(addr));
}
__device__ __forceinline__ void ldsm4t(unsigned& r0, unsigned& r1, unsigned& r2,
                                       unsigned& r3, unsigned addr) {
    asm volatile("ldmatrix.sync.aligned.m8n8.x4.trans.shared.b16 {%0,%1,%2,%3}, [%4];"
                 : "=r"(r0), "=r"(r1), "=r"(r2), "=r"(r3) : "r"(addr));
}
__device__ __forceinline__ void mma16816(float* c, const unsigned* a, const unsigned* b) {
    asm volatile("mma.sync.aligned.m16n8k16.row.col.f32.bf16.bf16.f32 "
                 "{%0,%1,%2,%3}, {%4,%5,%6,%7}, {%8,%9}, {%0,%1,%2,%3};"
                 : "+f"(c[0]), "+f"(c[1]), "+f"(c[2]), "+f"(c[3])
                 : "r"(a[0]), "r"(a[1]), "r"(a[2]), "r"(a[3]), "r"(b[0]), "r"(b[1]));
}
// split float4 into packed hi (2x u32) and lo (2x u32), pairwise cvt
__device__ __forceinline__ void cvt_split4(float4 v, uint2& hi, uint2& lo) {
    __nv_bfloat162 h01 = __float22bfloat162_rn(make_float2(v.x, v.y));
    __nv_bfloat162 h23 = __float22bfloat162_rn(make_float2(v.z, v.w));
    float2 f01 = __bfloat1622float2(h01);
    float2 f23 = __bfloat1622float2(h23);
    __nv_bfloat162 l01 = __float22bfloat162_rn(make_float2(v.x - f01.x, v.y - f01.y));
    __nv_bfloat162 l23 = __float22bfloat162_rn(make_float2(v.z - f23.x, v.w - f23.y));
    hi.x = *reinterpret_cast<unsigned*>(&h01);
    hi.y = *reinterpret_cast<unsigned*>(&h23);
    lo.x = *reinterpret_cast<unsigned*>(&l01);
    lo.y = *reinterpret_cast<unsigned*>(&l23);
}
__device__ __forceinline__ float silu_f(float v) { return v / (1.0f + expf(-v)); }

// ---------------- gating: fp64-accurate logits -> sortable 64-bit keys ------
__global__ void gate_kernel(const float* __restrict__ x,
                            const float* __restrict__ gw) {
    int t = blockIdx.x;
    int tid = threadIdx.x;
    double acc[E_NUM];
#pragma unroll
    for (int e = 0; e < E_NUM; ++e) acc[e] = 0.0;
    const float* xr = x + (size_t)t * H_DIM;
    for (int h = tid; h < H_DIM; h += 256) {
        double xv = (double)xr[h];
        const float* g = gw + h * E_NUM;
#pragma unroll
        for (int e = 0; e < E_NUM; ++e) acc[e] += xv * (double)g[e];
    }
#pragma unroll
    for (int e = 0; e < E_NUM; ++e) {
#pragma unroll
        for (int off = 16; off > 0; off >>= 1)
            acc[e] += __shfl_down_sync(0xffffffffu, acc[e], off);
    }
    __shared__ double red[8][E_NUM];
    int warp = tid >> 5, lane = tid & 31;
    if (lane == 0) {
#pragma unroll
        for (int e = 0; e < E_NUM; ++e) red[warp][e] = acc[e];
    }
    __syncthreads();
    if (tid < E_NUM) {
        double s = 0.0;
        for (int w = 0; w < 8; ++w) s += red[w][tid];
        float lf = (float)s;
        unsigned u = __float_as_uint(lf);
        u = (u & 0x80000000u) ? ~u : (u | 0x80000000u);
        unsigned long long key =
            ((unsigned long long)u << 13) | (unsigned)(8191 - t);
        g_keys[tid * N_TOK + t] = key;
        g_slot[t * E_NUM + tid] = -1;
    }
}

// ---------------- per-expert half-sort (bitonic, 4096 elems) ----------------
__global__ void sort_half_kernel() {
    __shared__ unsigned long long s[4096];
    int e = blockIdx.y, half = blockIdx.x;
    const unsigned long long* keys = g_keys + e * N_TOK + half * 4096;
    for (int i = threadIdx.x; i < 4096; i += 1024) s[i] = ~keys[i];
    __syncthreads();
    for (int k = 2; k <= 4096; k <<= 1) {
        for (int j = k >> 1; j > 0; j >>= 1) {
            for (int base = 0; base < 4096; base += 1024) {
                int i = base + threadIdx.x;
                int l = i ^ j;
                if (l > i) {
                    unsigned long long a = s[i], b = s[l];
                    bool up = ((i & k) == 0);
                    if (up ? (a > b) : (a < b)) { s[i] = b; s[l] = a; }
                }
            }
            __syncthreads();
        }
    }
    for (int i = threadIdx.x; i < K_CAP; i += 1024)
        g_part[(e * 2 + half) * K_CAP + i] = ~s[i];
}

// ---------------- merge the two sorted half-lists by rank -------------------
__global__ void merge_topk_kernel() {
    int e = blockIdx.x;
    const unsigned long long* A = g_part + (size_t)(e * 2 + 0) * K_CAP;
    const unsigned long long* B = g_part + (size_t)(e * 2 + 1) * K_CAP;
    for (int idx = threadIdx.x; idx < 2 * K_CAP; idx += blockDim.x) {
        bool inA = idx < K_CAP;
        const unsigned long long* other = inA ? B : A;
        int i = inA ? idx : idx - K_CAP;
        unsigned long long v = (inA ? A : B)[i];
        int lo = 0, hi = K_CAP;
        while (lo < hi) {
            int mid = (lo + hi) >> 1;
            if (other[mid] > v) lo = mid + 1; else hi = mid;
        }
        int rank = i + lo;
        if (rank < K_CAP) {
            int t = 8191 - (int)(v & 0x1FFFull);
            g_indices[e * K_CAP + rank] = t;
            g_slot[t * E_NUM + e] = rank;
        }
    }
}

// ---------------- HMMA GEMM: 128x128 tile, BK=32, 4 warps (64x64 each) ------
// A smem (hi/lo): [128 m][32 k] bf16, 64B rows, unit swizzle u^=(m&3)
// B smem (hi/lo): [32 k][128 n] bf16, 256B rows, unit swizzle u^=(k&7)
// KSPLIT: GEMM2 splits K into 2 halves writing separate g_eo planes.
template<bool FIRST, int KSPLIT>
__global__ __launch_bounds__(128, 2)
void moe_gemm_kernel(const float* __restrict__ x,
                     const float* __restrict__ w) {
    constexpr int KTOT = FIRST ? H_DIM : F_DIM;
    constexpr int KLOC = KTOT / KSPLIT;
    constexpr int NEXP = FIRST ? F_DIM : H_DIM;
    constexpr int NCH  = KLOC / 32;

    __shared__ __align__(16) unsigned char smA[2][8192];
    __shared__ __align__(16) unsigned char smB[2][8192];
    __shared__ int stok[128];

    const int tid  = threadIdx.x;
    const int wid  = tid >> 5, lane = tid & 31;
    const int e    = blockIdx.z / KSPLIT;
    const int kh   = blockIdx.z % KSPLIT;
    const int m0   = blockIdx.y * 128, n0 = blockIdx.x * 128;
    const int wm   = (wid >> 1) * 64;
    const int wn   = (wid & 1) * 64;

    const unsigned baseAh = smem_u32(smA[0]), baseAl = smem_u32(smA[1]);
    const unsigned baseBh = smem_u32(smB[0]), baseBl = smem_u32(smB[1]);

    if (FIRST) stok[tid] = g_indices[e * K_CAP + m0 + tid];
    __syncthreads();

    // ---- staging maps (fully coalesced: each warp-j covers 512B contiguous) --
    const int af     = tid & 7;    // A: 16B fp32 unit within row (k = af*4..+4)
    const int arow_g = tid >> 3;   // A: row = j*16 + arow_g
    const int bc     = tid & 31;   // B: col block (cols bc*4..+4)
    const int brow_g = tid >> 5;   // B: row = brow_g*8 + j

    const float* abase[8];
#pragma unroll
    for (int j = 0; j < 8; ++j) {
        int row = j * 16 + arow_g;
        if (FIRST)
            abase[j] = x + (size_t)stok[row] * H_DIM + kh * KLOC + af * 4;
        else
            abase[j] = g_h + ((size_t)e * K_CAP + m0 + row) * F_DIM + kh * KLOC + af * 4;
    }
    const float* bbase = w + (size_t)e * KTOT * NEXP
                         + (size_t)(kh * KLOC + brow_g * 8) * NEXP + n0 + bc * 4;

    float acc[4][8][4];
#pragma unroll
    for (int mt = 0; mt < 4; ++mt)
#pragma unroll
        for (int nt = 0; nt < 8; ++nt)
#pragma unroll
            for (int q = 0; q < 4; ++q) acc[mt][nt][q] = 0.0f;

    for (int kt = 0; kt < NCH; ++kt) {
        __syncthreads();
        // ---- stage A ----
#pragma unroll
        for (int j = 0; j < 8; ++j) {
            int row = j * 16 + arow_g;
            float4 v = *(const float4*)(abase[j] + kt * 32);
            uint2 hi, lo;
            cvt_split4(v, hi, lo);
            unsigned addr = (unsigned)row * 64u
                          + ((((unsigned)af >> 1) ^ ((unsigned)row & 3u)) * 16u)
                          + (af & 1) * 8u;
            *(uint2*)(smA[0] + addr) = hi;
            *(uint2*)(smA[1] + addr) = lo;
        }
        // ---- stage B ----
#pragma unroll
        for (int j = 0; j < 8; ++j) {
            int row = brow_g * 8 + j;
            float4 v = *(const float4*)(bbase + (size_t)(kt * 32 + j) * NEXP);
            uint2 hi, lo;
            cvt_split4(v, hi, lo);
            unsigned unit = (unsigned)bc >> 1;
            unsigned addr = (unsigned)row * 256u
                          + ((unit ^ ((unsigned)row & 7u)) * 16u)
                          + (bc & 1) * 8u;
            *(uint2*)(smB[0] + addr) = hi;
            *(uint2*)(smB[1] + addr) = lo;
        }
        __syncthreads();

        // ---- compute: 2 k16 steps, 3-term split ----
#pragma unroll
        for (int ks = 0; ks < 2; ++ks) {
            unsigned ah[4][4], al[4][4];
#pragma unroll
            for (int mt = 0; mt < 4; ++mt) {
                unsigned row = (unsigned)(wm + mt * 16 + (lane & 15));
                unsigned unit = (unsigned)(ks * 2 + (lane >> 4));
                unsigned off = row * 64u + ((unit ^ (row & 3u)) * 16u);
                ldsm4(ah[mt][0], ah[mt][1], ah[mt][2], ah[mt][3], baseAh + off);
                ldsm4(al[mt][0], al[mt][1], al[mt][2], al[mt][3], baseAl + off);
            }
            unsigned bh[8][2], bl[8][2];
#pragma unroll
            for (int p = 0; p < 4; ++p) {
                int g = lane >> 3;
                unsigned krow = (unsigned)(ks * 16 + (g & 1) * 8 + (lane & 7));
                unsigned unit = (unsigned)((wn >> 3) + 2 * p + (g >> 1));
                unsigned off = krow * 256u + ((unit ^ (krow & 7u)) * 16u);
                unsigned r0, r1, r2, r3;
                ldsm4t(r0, r1, r2, r3, baseBh + off);
                bh[2 * p][0] = r0;     bh[2 * p][1] = r1;
                bh[2 * p + 1][0] = r2; bh[2 * p + 1][1] = r3;
                ldsm4t(r0, r1, r2, r3, baseBl + off);
                bl[2 * p][0] = r0;     bl[2 * p][1] = r1;
                bl[2 * p + 1][0] = r2; bl[2 * p + 1][1] = r3;
            }
#pragma unroll
            for (int mt = 0; mt < 4; ++mt)
#pragma unroll
                for (int nt = 0; nt < 8; ++nt) {
                    mma16816(acc[mt][nt], ah[mt], bh[nt]);
                    mma16816(acc[mt][nt], al[mt], bh[nt]);
                    mma16816(acc[mt][nt], ah[mt], bl[nt]);
                }
        }
    }

    // ---- epilogue ----
#pragma unroll
    for (int mt = 0; mt < 4; ++mt) {
#pragma unroll
        for (int nt = 0; nt < 8; ++nt) {
            int row0 = m0 + wm + mt * 16 + (lane >> 2);
            int cc   = n0 + wn + nt * 8 + 2 * (lane & 3);
#pragma unroll
            for (int hrow = 0; hrow < 2; ++hrow) {
                float v0 = acc[mt][nt][2 * hrow + 0];
                float v1 = acc[mt][nt][2 * hrow + 1];
                if (FIRST) {
                    size_t g0 = ((size_t)e * K_CAP + row0 + 8 * hrow) * (size_t)F_DIM + cc;
                    float2 s;
                    s.x = silu_f(v0);
                    s.y = silu_f(v1);
                    *(float2*)(g_h + g0) = s;
                } else {
                    size_t g0 = kh * EOP
                              + ((size_t)e * K_CAP + row0 + 8 * hrow) * (size_t)H_DIM + cc;
                    float2 s;
                    s.x = v0;
                    s.y = v1;
                    *(float2*)(g_eo + g0) = s;
                }
            }
        }
    }
}

// ---------------- deterministic scatter (sums both split-K planes) ----------
__global__ void scatter_kernel(float* __restrict__ out) {
    int t = blockIdx.x, tid = threadIdx.x;
    __shared__ int ssl[E_NUM];
    if (tid < E_NUM) ssl[tid] = g_slot[t * E_NUM + tid];
    __syncthreads();
    int j = tid * 4;
    float4 sum = make_float4(0.f, 0.f, 0.f, 0.f);
#pragma unroll
    for (int e = 0; e < E_NUM; ++e) {
        int sl = ssl[e];
        if (sl >= 0) {
            size_t base = ((size_t)e * K_CAP + sl) * H_DIM + j;
            float4 v0 = *(const float4*)(g_eo + base);
            float4 v1 = *(const float4*)(g_eo + EOP + base);
            sum.x += v0.x + v1.x; sum.y += v0.y + v1.y;
            sum.z += v0.z + v1.z; sum.w += v0.w + v1.w;
        }
    }
    *(float4*)(out + (size_t)t * H_DIM + j) = sum;
}

// ---------------- launch ----------------------------------------------------
extern "C" void kernel_launch(void* const* d_in, const int* in_sizes, int n_in,
                              void* d_out, int out_size) {
    const float* x  = (const float*)d_in[0];   // [4,2048,1024]
    const float* gw = (const float*)d_in[1];   // [1024,8]
    const float* w1 = (const float*)d_in[2];   // [8,1024,4096]
    const float* w2 = (const float*)d_in[3];   // [8,4096,1024]
    float* out = (float*)d_out;
    (void)in_sizes; (void)n_in;

    // loss scalar = 0 exactly (expert_load == k for all experts)
    cudaMemsetAsync(d_out, 0, (size_t)out_size * sizeof(float), 0);

    gate_kernel<<<N_TOK, 256>>>(x, gw);
    sort_half_kernel<<<dim3(2, E_NUM), 1024>>>();
    merge_topk_kernel<<<E_NUM, 256>>>();

    moe_gemm_kernel<true, 1><<<dim3(F_DIM / 128, K_CAP / 128, E_NUM), 128>>>(x, w1);
    moe_gemm_kernel<false, 2><<<dim3(H_DIM / 128, K_CAP / 128, E_NUM * 2), 128>>>(nullptr, w2);

    scatter_kernel<<<N_TOK, 256>>>(out);
}